// round 1
// baseline (speedup 1.0000x reference)
#include <cuda_runtime.h>
#include <math.h>

// ---------------- problem constants ----------------
#define Bn   256
#define Tn   512
#define INn  32
#define Hn   128
#define Sn   4
#define HQn  32
#define BTn  (Bn*Tn)          // 131072 positions
#define DTC  0.1f

typedef unsigned long long u64;

// ---------------- scratch (static device globals; no allocation) ----------------
__device__ float g_xp  [(size_t)BTn*Hn];        //  64 MB  x @ Wp.T + bp
__device__ float g_inp [(size_t)Sn*BTn*Hn];     // 268 MB  per-scale input drive (incl. biases)
__device__ float g_itau[(size_t)Sn*BTn*Hn];     // 268 MB  per-scale 1/tau
__device__ float g_hT  [Sn*Bn*Hn];              // final hidden states

// ---------------- packed fp32x2 helpers (Blackwell FFMA2) ----------------
__device__ __forceinline__ void ffma2(u64 &d, u64 a, u64 b) {
    asm("fma.rn.f32x2 %0, %1, %2, %0;" : "+l"(d) : "l"(a), "l"(b));
}
__device__ __forceinline__ float hsum2(u64 a0, u64 a1) {
    float x0, y0, x1, y1;
    asm("mov.b64 {%0,%1}, %2;" : "=f"(x0), "=f"(y0) : "l"(a0));
    asm("mov.b64 {%0,%1}, %2;" : "=f"(x1), "=f"(y1) : "l"(a1));
    return (x0 + x1) + (y0 + y1);
}

// ============================================================================
// K1: x_proj[pos, i] = x[pos, :32] @ Wp[i, :32] + bp[i]
// CTA = 128 threads (thread = output channel), 32 positions per CTA.
// ============================================================================
__global__ void __launch_bounds__(128) k_xp(const float* __restrict__ x,
                                            const float* __restrict__ Wp,
                                            const float* __restrict__ bp) {
    const int i  = threadIdx.x;
    const int p0 = blockIdx.x * 32;
    __shared__ float xs[32][INn];

    // load x tile (1024 floats = 256 float4)
    const float4* src = (const float4*)(x + (size_t)p0 * INn);
    float4* dst = (float4*)&xs[0][0];
    dst[i]       = src[i];
    dst[i + 128] = src[i + 128];

    // Wp row i in registers as 16 packed pairs
    u64 w[16];
    const u64* wq = (const u64*)(Wp + (size_t)i * INn);
#pragma unroll
    for (int m = 0; m < 16; m++) w[m] = wq[m];
    const float bias = bp[i];
    __syncthreads();

#pragma unroll 4
    for (int p = 0; p < 32; p++) {
        const u64* xq = (const u64*)&xs[p][0];
        u64 a0 = 0ull, a1 = 0ull;
#pragma unroll
        for (int m = 0; m < 16; m += 2) { ffma2(a0, w[m], xq[m]); ffma2(a1, w[m + 1], xq[m + 1]); }
        g_xp[(size_t)(p0 + p) * Hn + i] = hsum2(a0, a1) + bias;
    }
}

// ============================================================================
// K2: inp[s,pos,i] = xp[pos,:] @ Win_w[s,i,:] + Win_b[s,i] + cbias[s,i]
// grid = (BT/32, S), CTA = 128 threads, W row in registers (64 packed pairs).
// ============================================================================
__global__ void __launch_bounds__(128) k_inp(const float* __restrict__ Win_w,
                                             const float* __restrict__ Win_b,
                                             const float* __restrict__ cbias) {
    const int i  = threadIdx.x;
    const int s  = blockIdx.y;
    const int p0 = blockIdx.x * 32;
    __shared__ float xs[32][Hn];

    // load xp tile (4096 floats = 1024 float4)
    const float4* src = (const float4*)(g_xp + (size_t)p0 * Hn);
    float4* dst = (float4*)&xs[0][0];
#pragma unroll
    for (int r = i; r < 1024; r += 128) dst[r] = src[r];

    u64 w[64];
    const u64* wq = (const u64*)(Win_w + ((size_t)s * Hn + i) * Hn);
#pragma unroll
    for (int m = 0; m < 64; m++) w[m] = wq[m];
    const float bias = Win_b[s * Hn + i] + cbias[s * Hn + i];
    __syncthreads();

    float* outp = g_inp + ((size_t)s * BTn + p0) * Hn + i;
    for (int p = 0; p < 32; p++) {
        const u64* xq = (const u64*)&xs[p][0];
        u64 a0 = 0ull, a1 = 0ull;
#pragma unroll
        for (int m = 0; m < 64; m += 2) { ffma2(a0, w[m], xq[m]); ffma2(a1, w[m + 1], xq[m + 1]); }
        outp[(size_t)p * Hn] = hsum2(a0, a1) + bias;
    }
}

// ============================================================================
// K3: volatility gate -> itau[s,pos,i]
//   g   = relu(xp @ v1w[s].T + v1b[s])            [32]
//   vol = sigmoid(g @ v2w[s].T + v2b[s])          [128]
//   itau = 1 / clip(tb * (0.2 + 1.8*(1-vol)), 0.1, 10)
// ============================================================================
__global__ void __launch_bounds__(128) k_itau(const float* __restrict__ v1w,
                                              const float* __restrict__ v1b,
                                              const float* __restrict__ v2w,
                                              const float* __restrict__ v2b,
                                              const float* __restrict__ tau_base) {
    const int i  = threadIdx.x;
    const int s  = blockIdx.y;
    const int p0 = blockIdx.x * 32;
    __shared__ float xs[32][Hn];
    __shared__ float gs[32][HQn];

    const float4* src = (const float4*)(g_xp + (size_t)p0 * Hn);
    float4* dst = (float4*)&xs[0][0];
#pragma unroll
    for (int r = i; r < 1024; r += 128) dst[r] = src[r];
    __syncthreads();

    // ---- stage 1: g (32 outputs). warp = position group, lane = q ----
    {
        const int q   = i & 31;
        const int grp = i >> 5;
        u64 wv[64];
        const u64* wq = (const u64*)(v1w + ((size_t)s * HQn + q) * Hn);
#pragma unroll
        for (int m = 0; m < 64; m++) wv[m] = wq[m];
        const float b1 = v1b[s * HQn + q];
        for (int pp = 0; pp < 8; pp++) {
            const int p = grp * 8 + pp;
            const u64* xq = (const u64*)&xs[p][0];
            u64 a0 = 0ull, a1 = 0ull;
#pragma unroll
            for (int m = 0; m < 64; m += 2) { ffma2(a0, wv[m], xq[m]); ffma2(a1, wv[m + 1], xq[m + 1]); }
            gs[p][q] = fmaxf(hsum2(a0, a1) + b1, 0.f);
        }
    }
    __syncthreads();

    // ---- stage 2: vol -> itau ----
    {
        u64 w2[16];
        const u64* wq = (const u64*)(v2w + ((size_t)s * Hn + i) * HQn);
#pragma unroll
        for (int m = 0; m < 16; m++) w2[m] = wq[m];
        const float b2 = v2b[s * Hn + i];
        const float tb = tau_base[s * Hn + i];
        float* outp = g_itau + ((size_t)s * BTn + p0) * Hn + i;
        for (int p = 0; p < 32; p++) {
            const u64* gq = (const u64*)&gs[p][0];
            u64 a0 = 0ull, a1 = 0ull;
#pragma unroll
            for (int m = 0; m < 16; m += 2) { ffma2(a0, w2[m], gq[m]); ffma2(a1, w2[m + 1], gq[m + 1]); }
            const float z   = hsum2(a0, a1) + b2;
            const float vol = 1.f / (1.f + expf(-z));
            float tau = tb * (0.2f + 1.8f * (1.f - vol));
            tau = fminf(fmaxf(tau, 0.1f), 10.f);
            outp[(size_t)p * Hn] = 1.f / tau;
        }
    }
}

// ============================================================================
// K4: liquid-cell scan. One CTA (128 threads) per (scale, batch row).
// Thread i owns channel i; Wrec row i lives in registers as 64 packed pairs.
// Inner step: 32x LDS.64 broadcast of h + 64x fma.rn.f32x2, then tanh,
// block-norm, Euler update. 2 __syncthreads per inner step.
// ============================================================================
__global__ void __launch_bounds__(128) k_scan(const float* __restrict__ Wrec) {
    const int bid  = blockIdx.x;
    const int s    = bid >> 8;       // 0..3  (stride-148 SM placement mixes scales per SM)
    const int b    = bid & 255;
    const int i    = threadIdx.x;
    const int lane = i & 31, wid = i >> 5;

    __shared__ float h_s[Hn];
    __shared__ float red[4];

    u64 w[64];
    const u64* wq = (const u64*)(Wrec + ((size_t)s * Hn + i) * Hn);
#pragma unroll
    for (int m = 0; m < 64; m++) w[m] = wq[m];

    float h = 0.f;
    h_s[i] = 0.f;
    const int nsteps = 3 + 2 * s;
    const float* inp_ptr  = g_inp  + ((size_t)(s * Bn + b)) * Tn * Hn + i;
    const float* itau_ptr = g_itau + ((size_t)(s * Bn + b)) * Tn * Hn + i;
    __syncthreads();

    float inp  = inp_ptr[0];
    float itau = itau_ptr[0];
    for (int t = 0; t < Tn; t++) {
        // prefetch next timestep's drive while inner steps run
        const int tn = (t + 1 < Tn) ? t + 1 : t;
        const float ninp  = inp_ptr [(size_t)tn * Hn];
        const float nitau = itau_ptr[(size_t)tn * Hn];

        for (int k = 0; k < nsteps; k++) {
            // target_i = tanh( sum_j h_j * W[i][j] + inp_i )
            const u64* hq = (const u64*)h_s;
            u64 a0 = 0ull, a1 = 0ull;
#pragma unroll
            for (int m = 0; m < 64; m += 2) { ffma2(a0, w[m], hq[m]); ffma2(a1, w[m + 1], hq[m + 1]); }
            const float target = tanhf(hsum2(a0, a1) + inp);
            const float dh = (target - h) * itau;

            // ||dhdt|| over all 128 channels
            float sq = dh * dh;
#pragma unroll
            for (int off = 16; off; off >>= 1) sq += __shfl_xor_sync(0xffffffffu, sq, off);
            if (lane == 0) red[wid] = sq;
            __syncthreads();
            const float mag = sqrtf((red[0] + red[1]) + (red[2] + red[3]));
            const float sc  = DTC / (1.f + 0.2f * mag);
            h = h + sc * dh;
            h_s[i] = h;
            __syncthreads();
        }
        inp = ninp; itau = nitau;
    }
    g_hT[((size_t)(s * Bn + b)) * Hn + i] = h;
}

// ============================================================================
// K5: projection heads + fusion MLP. One CTA per batch row.
// ============================================================================
__global__ void __launch_bounds__(128) k_head(const float* __restrict__ proj_w,
                                              const float* __restrict__ proj_b,
                                              const float* __restrict__ f1_w,
                                              const float* __restrict__ f1_b,
                                              const float* __restrict__ f2_w,
                                              const float* __restrict__ f2_b,
                                              const float* __restrict__ f3_w,
                                              const float* __restrict__ f3_b,
                                              float* __restrict__ out) {
    const int b = blockIdx.x;
    const int i = threadIdx.x;
    __shared__ float fs[Hn];
    __shared__ float h1s[Hn];
    __shared__ float h2s[64];
    __shared__ float rs[4];

    // feat: thread i -> scale s=i/32, unit q=i%32
    {
        const int s = i >> 5, q = i & 31;
        const float* hrow = g_hT + (size_t)(s * Bn + b) * Hn;
        const float* pw   = proj_w + (size_t)(s * 32 + q) * Hn;
        float acc = proj_b[s * 32 + q];
#pragma unroll 8
        for (int j = 0; j < Hn; j++) acc += hrow[j] * pw[j];
        fs[i] = acc;
    }
    __syncthreads();

    // f1 + relu
    {
        const float* w1 = f1_w + (size_t)i * Hn;
        float acc = f1_b[i];
#pragma unroll 8
        for (int j = 0; j < Hn; j++) acc += fs[j] * w1[j];
        h1s[i] = fmaxf(acc, 0.f);
    }
    __syncthreads();

    // f2 + relu (64 outputs)
    if (i < 64) {
        const float* w2 = f2_w + (size_t)i * Hn;
        float acc = f2_b[i];
#pragma unroll 8
        for (int j = 0; j < Hn; j++) acc += h1s[j] * w2[j];
        h2s[i] = fmaxf(acc, 0.f);
    }
    __syncthreads();

    // f3: dot over 64
    float pr = (i < 64) ? h2s[i] * f3_w[i] : 0.f;
#pragma unroll
    for (int off = 16; off; off >>= 1) pr += __shfl_xor_sync(0xffffffffu, pr, off);
    if ((i & 31) == 0) rs[i >> 5] = pr;
    __syncthreads();
    if (i == 0) out[b] = rs[0] + rs[1] + f3_b[0];
}

// ============================================================================
extern "C" void kernel_launch(void* const* d_in, const int* in_sizes, int n_in,
                              void* d_out, int out_size) {
    (void)in_sizes; (void)n_in; (void)out_size;
    const float* x        = (const float*)d_in[0];
    const float* Wp       = (const float*)d_in[1];
    const float* bp       = (const float*)d_in[2];
    const float* Wrec     = (const float*)d_in[3];
    const float* Win_w    = (const float*)d_in[4];
    const float* Win_b    = (const float*)d_in[5];
    const float* cbias    = (const float*)d_in[6];
    const float* tau_base = (const float*)d_in[7];
    const float* vg1_w    = (const float*)d_in[8];
    const float* vg1_b    = (const float*)d_in[9];
    const float* vg2_w    = (const float*)d_in[10];
    const float* vg2_b    = (const float*)d_in[11];
    const float* proj_w   = (const float*)d_in[12];
    const float* proj_b   = (const float*)d_in[13];
    const float* f1_w     = (const float*)d_in[14];
    const float* f1_b     = (const float*)d_in[15];
    const float* f2_w     = (const float*)d_in[16];
    const float* f2_b     = (const float*)d_in[17];
    const float* f3_w     = (const float*)d_in[18];
    const float* f3_b     = (const float*)d_in[19];
    float* out = (float*)d_out;

    k_xp  <<<BTn / 32, 128>>>(x, Wp, bp);
    k_inp <<<dim3(BTn / 32, Sn), 128>>>(Win_w, Win_b, cbias);
    k_itau<<<dim3(BTn / 32, Sn), 128>>>(vg1_w, vg1_b, vg2_w, vg2_b, tau_base);
    k_scan<<<Sn * Bn, 128>>>(Wrec);
    k_head<<<Bn, 128>>>(proj_w, proj_b, f1_w, f1_b, f2_w, f2_b, f3_w, f3_b, out);
}